// round 10
// baseline (speedup 1.0000x reference)
#include <cuda_runtime.h>
#include <cstdint>

// Chamfer distance: B=8, N=M=4096, D=3 — bidirectional, scalar FFMA, round 10.
// R10 = R9 with grid 1024 in ONE resident wave (PCHUNK=128, 7 blocks/SM cap)
// to fix grid-limited occupancy (R9: 3.46 blocks/SM, issue 64%).

constexpr int B       = 8;
constexpr int NPTS    = 4096;
constexpr int THREADS = 128;
constexpr int GPT     = 8;                       // resident gts per thread
constexpr int GTSB    = THREADS * GPT;           // 1024 gts per block
constexpr int GS      = NPTS / GTSB;             // 4 gt splits
constexpr int PCHUNK  = 128;                     // preds streamed per block
constexpr int PC      = NPTS / PCHUNK;           // 32 pred chunks
constexpr int NBLOCKS = B * PC * GS;             // 1024 (single wave @7/SM)
constexpr int GRP     = 16;                      // preds per transpose group

__device__ float        g_colpart[B * PC * NPTS];  // [b][pc][gt] unclamped
__device__ float        g_rowpart[B * GS * NPTS];  // [b][gs][pred] unclamped
__device__ float        g_batch[B];
__device__ unsigned int g_cnt_batch[B];
__device__ unsigned int g_cnt_final;

__global__ __launch_bounds__(THREADS, 7) void chamfer_bidir(
    const float* __restrict__ pred, const float* __restrict__ gt,
    float* __restrict__ out)
{
    __shared__ float4 sp[PCHUNK];             // {-2px,-2py,-2pz,x2}  2KB
    __shared__ float  srow[PCHUNK][4];        // per-pred per-warp row mins 2KB
    __shared__ float  sred[4];
    __shared__ int    s_e1, s_e2;

    const int bx  = blockIdx.x;
    const int gs  = bx & (GS - 1);
    const int pc  = (bx >> 2) & (PC - 1);
    const int b   = bx >> 7;
    const int tid = threadIdx.x;
    const int wid = tid >> 5, lid = tid & 31;

    // ---- stage 128 preds (1 per thread) ----
    {
        const float* p = pred + (size_t)b * NPTS * 3 + (size_t)(pc * PCHUNK + tid) * 3;
        const float px = p[0], py = p[1], pz = p[2];
        const float x2 = fmaf(px, px, fmaf(py, py, pz * pz));
        sp[tid] = make_float4(-2.f * px, -2.f * py, -2.f * pz, x2);
    }

    // ---- resident gt points: 8 scalars ----
    float gx[GPT], gy[GPT], gz[GPT], gw[GPT];
    {
        const float2* g = reinterpret_cast<const float2*>(
            gt + (size_t)b * NPTS * 3 + (size_t)(gs * GTSB + tid * GPT) * 3);
        #pragma unroll
        for (int q = 0; q < GPT / 2; ++q) {
            const float2 a = g[3 * q + 0];   // x0 y0
            const float2 c = g[3 * q + 1];   // z0 x1
            const float2 e = g[3 * q + 2];   // y1 z1
            gx[2 * q + 0] = a.x; gy[2 * q + 0] = a.y; gz[2 * q + 0] = c.x;
            gx[2 * q + 1] = c.y; gy[2 * q + 1] = e.x; gz[2 * q + 1] = e.y;
            gw[2 * q + 0] = fmaf(a.x, a.x, fmaf(a.y, a.y, c.x * c.x));
            gw[2 * q + 1] = fmaf(c.y, c.y, fmaf(e.x, e.x, e.y * e.y));
        }
    }
    __syncthreads();

    float cmin[GPT];
    #pragma unroll
    for (int i = 0; i < GPT; ++i) cmin[i] = 3.4e38f;

    // ---- main loop: 8 groups x 16 preds ----
    for (int grp = 0; grp < PCHUNK / GRP; ++grp) {
        float a[GRP];
        #pragma unroll
        for (int i = 0; i < GRP; ++i) {
            const float4 P = sp[grp * GRP + i];    // broadcast LDS.128
            float u[GPT];
            #pragma unroll
            for (int q = 0; q < GPT; ++q) {
                float t = fmaf(P.z, gz[q], gw[q]);
                t = fmaf(P.y, gy[q], t);
                t = fmaf(P.x, gx[q], t);
                u[q] = t + P.w;                    // full |p-g|^2 (unclamped)
                cmin[q] = fminf(cmin[q], u[q]);
            }
            const float m0 = fminf(fminf(u[0], u[1]), fminf(u[2], u[3]));
            const float m1 = fminf(fminf(u[4], u[5]), fminf(u[6], u[7]));
            a[i] = fminf(m0, m1);
        }
        // Butterfly transpose-reduce: lane lid ends with warp-min for pred
        // grp*16 + (lid & 15).
        #pragma unroll
        for (int k = 1; k <= 8; k <<= 1) {
            const bool up = (lid & k) != 0;
            #pragma unroll
            for (int m = 0; m < GRP / (2 * k); ++m) {
                const float send = up ? a[2 * m] : a[2 * m + 1];
                const float t    = __shfl_xor_sync(0xffffffffu, send, k);
                a[m] = fminf(up ? a[2 * m + 1] : a[2 * m], t);
            }
        }
        a[0] = fminf(a[0], __shfl_xor_sync(0xffffffffu, a[0], 16));
        if (lid < GRP) srow[grp * GRP + lid][wid] = a[0];
    }
    __syncthreads();

    // ---- cross-warp row combine -> global row partials (1 pred/thread) ----
    {
        const float4 v = *reinterpret_cast<const float4*>(srow[tid]);
        g_rowpart[(size_t)(b * GS + gs) * NPTS + pc * PCHUNK + tid] =
            fminf(fminf(v.x, v.y), fminf(v.z, v.w));
    }

    // ---- col partials -> global ----
    {
        float* cp = g_colpart + (size_t)(b * PC + pc) * NPTS + gs * GTSB + tid * GPT;
        reinterpret_cast<float4*>(cp)[0] = make_float4(cmin[0], cmin[1], cmin[2], cmin[3]);
        reinterpret_cast<float4*>(cp)[1] = make_float4(cmin[4], cmin[5], cmin[6], cmin[7]);
    }

    // ---- per-batch election (last of PC*GS = 128 blocks) ----
    __threadfence();
    if (tid == 0)
        s_e1 = (atomicAdd(&g_cnt_batch[b], 1u) == (unsigned)(PC * GS - 1));
    __syncthreads();
    if (!s_e1) return;
    __threadfence();

    {
        float sum = 0.0f;
        const float4* cpb = reinterpret_cast<const float4*>(g_colpart + (size_t)b * PC * NPTS);
        for (int g4 = tid; g4 < NPTS / 4; g4 += THREADS) {
            float4 m = __ldcg(&cpb[g4]);
            #pragma unroll 8
            for (int k = 1; k < PC; ++k) {
                const float4 v = __ldcg(&cpb[(size_t)k * (NPTS / 4) + g4]);
                m.x = fminf(m.x, v.x); m.y = fminf(m.y, v.y);
                m.z = fminf(m.z, v.z); m.w = fminf(m.w, v.w);
            }
            sum += fmaxf(m.x, 0.f) + fmaxf(m.y, 0.f) + fmaxf(m.z, 0.f) + fmaxf(m.w, 0.f);
        }
        const float4* rpb = reinterpret_cast<const float4*>(g_rowpart + (size_t)b * GS * NPTS);
        for (int p4 = tid; p4 < NPTS / 4; p4 += THREADS) {
            float4 m = __ldcg(&rpb[p4]);
            #pragma unroll
            for (int k = 1; k < GS; ++k) {
                const float4 v = __ldcg(&rpb[(size_t)k * (NPTS / 4) + p4]);
                m.x = fminf(m.x, v.x); m.y = fminf(m.y, v.y);
                m.z = fminf(m.z, v.z); m.w = fminf(m.w, v.w);
            }
            sum += fmaxf(m.x, 0.f) + fmaxf(m.y, 0.f) + fmaxf(m.z, 0.f) + fmaxf(m.w, 0.f);
        }
        #pragma unroll
        for (int off = 16; off; off >>= 1)
            sum += __shfl_down_sync(0xffffffffu, sum, off);
        if (lid == 0) sred[wid] = sum;
        __syncthreads();
        if (tid == 0)
            g_batch[b] = (sred[0] + sred[1]) + (sred[2] + sred[3]);
    }
    __syncthreads();

    // ---- global election (last of 8 batch leaders) ----
    __threadfence();
    if (tid == 0)
        s_e2 = (atomicAdd(&g_cnt_final, 1u) == (unsigned)(B - 1));
    __syncthreads();
    if (!s_e2) return;

    if (tid == 0) {
        __threadfence();
        float s = 0.0f;
        #pragma unroll
        for (int i = 0; i < B; ++i) s += __ldcg(&g_batch[i]);
        out[0] = s * (1.0f / (float)(B * NPTS));
        g_cnt_final = 0;
        #pragma unroll
        for (int i = 0; i < B; ++i) g_cnt_batch[i] = 0;
    }
}

extern "C" void kernel_launch(void* const* d_in, const int* in_sizes, int n_in,
                              void* d_out, int out_size)
{
    const float* pred = (const float*)d_in[0];
    const float* gt   = (const float*)d_in[1];
    float* out        = (float*)d_out;

    chamfer_bidir<<<NBLOCKS, THREADS>>>(pred, gt, out);
}

// round 11
// speedup vs baseline: 1.0747x; 1.0747x over previous
#include <cuda_runtime.h>
#include <cstdint>

// Chamfer distance: B=8, N=M=4096, D=3 — unidirectional register-tiled, R11.
// R3's main loop ran AT the FFMA roofline; this round spreads it over all
// 148 SMs (144-block single wave) and fuses the finalize via election.
//
// Block (unit, ts): unit = (dir,b); full 4096 src points (8/thread), target
// slice of 456 staged in smem (9 splits, padded with +INF dummies).
// min_g |p-g|^2 = x2(p) + min_g(w(g) - 2 p.g), clamp >= 0 (commutes with min).

constexpr int B       = 8;
constexpr int NPTS    = 4096;
constexpr int THREADS = 512;
constexpr int R       = 8;                    // src points per thread (8*512=4096)
constexpr int UNITS   = 2 * B;                // 16 (dir, batch)
constexpr int TSPLIT  = 9;                    // target splits per unit
constexpr int TT      = 456;                  // staged targets (456*9=4104 >= 4096)
constexpr int NBLOCKS = UNITS * TSPLIT;       // 144 — single wave on 148 SMs

__device__ float        g_part[UNITS * TSPLIT * NPTS];  // clamped partial mins
__device__ float        g_unit[UNITS];
__device__ unsigned int g_cnt_unit[UNITS];
__device__ unsigned int g_cnt_final;

__global__ __launch_bounds__(THREADS) void chamfer_uni(
    const float* __restrict__ pred, const float* __restrict__ gt,
    float* __restrict__ out)
{
    __shared__ float4 s[TT];                  // {x, y, z, |g|^2}  7296B
    __shared__ float  sred[16];
    __shared__ int    s_e1, s_e2;

    const int bx   = blockIdx.x;
    const int unit = bx / TSPLIT;
    const int ts   = bx - unit * TSPLIT;
    const int dir  = unit >> 3;
    const int b    = unit & 7;
    const int tid  = threadIdx.x;
    const int wid  = tid >> 5, lid = tid & 31;

    const float* __restrict__ src = (dir == 0) ? pred : gt;
    const float* __restrict__ tgt = (dir == 0) ? gt   : pred;
    const float* sp = src + (size_t)b * NPTS * 3;
    const float* tp = tgt + (size_t)b * NPTS * 3;

    // ---- stage TT targets (pad out-of-range with +INF-w dummies) ----
    if (tid < TT) {
        const int gi = ts * TT + tid;
        if (gi < NPTS) {
            const float gx = tp[3 * gi + 0];
            const float gy = tp[3 * gi + 1];
            const float gz = tp[3 * gi + 2];
            s[tid] = make_float4(gx, gy, gz,
                                 fmaf(gx, gx, fmaf(gy, gy, gz * gz)));
        } else {
            s[tid] = make_float4(0.f, 0.f, 0.f, 3.4e38f);
        }
    }

    // ---- load R src points per thread ----
    float mx[R], my[R], mz[R], x2[R], bmin[R];
    #pragma unroll
    for (int k = 0; k < R; ++k) {
        const float* p = sp + (size_t)(tid + k * THREADS) * 3;
        const float px = p[0], py = p[1], pz = p[2];
        x2[k] = fmaf(px, px, fmaf(py, py, pz * pz));
        mx[k] = -2.0f * px;
        my[k] = -2.0f * py;
        mz[k] = -2.0f * pz;
        bmin[k] = 3.4e38f;
    }
    __syncthreads();

    // ---- main loop: 456 targets, unroll 4 (456 = 4*114) ----
    #pragma unroll 4
    for (int j = 0; j < TT; ++j) {
        const float4 G = s[j];                // broadcast LDS.128
        #pragma unroll
        for (int k = 0; k < R; ++k) {
            const float d = fmaf(mx[k], G.x,
                            fmaf(my[k], G.y,
                            fmaf(mz[k], G.z, G.w)));
            bmin[k] = fminf(bmin[k], d);
        }
    }

    // ---- clamped partial per src -> global (coalesced per k) ----
    {
        float* gp = g_part + (size_t)bx * NPTS;
        #pragma unroll
        for (int k = 0; k < R; ++k)
            gp[tid + k * THREADS] = fmaxf(x2[k] + bmin[k], 0.0f);
    }

    // ---- per-unit election: last of TSPLIT blocks combines the unit ----
    __threadfence();
    if (tid == 0)
        s_e1 = (atomicAdd(&g_cnt_unit[unit], 1u) == (unsigned)(TSPLIT - 1));
    __syncthreads();
    if (!s_e1) return;
    __threadfence();

    {
        const float* up = g_part + (size_t)unit * TSPLIT * NPTS;
        float sum = 0.0f;
        #pragma unroll
        for (int k = 0; k < R; ++k) {
            const int i = tid + k * THREADS;
            float m = __ldcg(up + i);
            #pragma unroll
            for (int t = 1; t < TSPLIT; ++t)
                m = fminf(m, __ldcg(up + (size_t)t * NPTS + i));
            sum += m;
        }
        #pragma unroll
        for (int off = 16; off; off >>= 1)
            sum += __shfl_down_sync(0xffffffffu, sum, off);
        if (lid == 0) sred[wid] = sum;
        __syncthreads();
        if (wid == 0) {
            float v = (lid < 16) ? sred[lid] : 0.0f;
            #pragma unroll
            for (int off = 8; off; off >>= 1)
                v += __shfl_down_sync(0xffffffffu, v, off);
            if (lid == 0) g_unit[unit] = v;
        }
    }

    // ---- global election: last of UNITS leaders writes the scalar ----
    __threadfence();
    if (tid == 0)
        s_e2 = (atomicAdd(&g_cnt_final, 1u) == (unsigned)(UNITS - 1));
    __syncthreads();
    if (!s_e2) return;

    if (wid == 0) {
        __threadfence();
        float v = (lid < UNITS) ? __ldcg(&g_unit[lid]) : 0.0f;
        #pragma unroll
        for (int off = 8; off; off >>= 1)
            v += __shfl_down_sync(0xffffffffu, v, off);
        if (lid == 0) {
            out[0] = v * (1.0f / (float)(B * NPTS));
            g_cnt_final = 0;
            #pragma unroll
            for (int i = 0; i < UNITS; ++i) g_cnt_unit[i] = 0;
        }
    }
}

extern "C" void kernel_launch(void* const* d_in, const int* in_sizes, int n_in,
                              void* d_out, int out_size)
{
    const float* pred = (const float*)d_in[0];
    const float* gt   = (const float*)d_in[1];
    float* out        = (float*)d_out;

    chamfer_uni<<<NBLOCKS, THREADS>>>(pred, gt, out);
}